// round 1
// baseline (speedup 1.0000x reference)
#include <cuda_runtime.h>
#include <math.h>

#define NMAX 50000
#define DDIM 64

// scratch for transformed features h = X @ W^T
__device__ float g_h[(size_t)NMAX * DDIM];

// ---------------------------------------------------------------------------
// Kernel 1: h = X @ W^T ; d_out = h * skip_weight + bias   (init accumulator)
// Block: 256 threads = 4 rows x 64 cols per iteration, 16 rows per block.
// ---------------------------------------------------------------------------
__global__ void __launch_bounds__(256) gemm_skip_kernel(
    const float* __restrict__ X,      // (N, 64)
    const float* __restrict__ W,      // (64, 64)  [o][d]
    const float* __restrict__ bias,   // (64)
    const float* __restrict__ skipw,  // (64)
    float* __restrict__ out,          // (N, 64) accumulator
    int n)
{
    __shared__ float sW[DDIM][DDIM + 1];   // [o][d], padded
    __shared__ float sX[16][DDIM + 1];     // 16 rows tile

    const int tid = threadIdx.x;

    // load W: 4096 floats / 256 threads = 16 each, coalesced
    #pragma unroll
    for (int i = 0; i < 16; i++) {
        int idx = tid + i * 256;
        int o = idx >> 6, d = idx & 63;
        sW[o][d] = W[idx];
    }

    const int o = tid & 63;         // output column
    const int rsub = tid >> 6;      // 0..3
    const float sw = skipw[o];
    const float bv = bias[o];

    const int row0 = blockIdx.x * 16;

    // load 16-row X tile: 1024 floats / 256 threads = 4 each
    #pragma unroll
    for (int i = 0; i < 4; i++) {
        int idx = tid + i * 256;
        int r = idx >> 6, d = idx & 63;
        int gr = row0 + r;
        sX[r][d] = (gr < n) ? X[(size_t)gr * DDIM + d] : 0.0f;
    }
    __syncthreads();

    #pragma unroll
    for (int rr = 0; rr < 4; rr++) {
        int r = rsub + rr * 4;
        int gr = row0 + r;
        if (gr < n) {
            float acc = 0.0f;
            #pragma unroll
            for (int d = 0; d < DDIM; d++) {
                acc = fmaf(sX[r][d], sW[o][d], acc);
            }
            g_h[(size_t)gr * DDIM + o] = acc;
            out[(size_t)gr * DDIM + o] = fmaf(acc, sw, bv);
        }
    }
}

// ---------------------------------------------------------------------------
// Kernel 2: scatter-add  out[dst] += h[src] * edge_weight
// 16 threads per edge, each handles 4 floats via float4 gather + 4 atomics.
// ---------------------------------------------------------------------------
__global__ void __launch_bounds__(256) scatter_kernel(
    const float* __restrict__ ew,
    const int*   __restrict__ src,
    const int*   __restrict__ dst,
    float* __restrict__ out,
    int E)
{
    int idx = blockIdx.x * blockDim.x + threadIdx.x;
    int e = idx >> 4;
    if (e >= E) return;
    int lane4 = (idx & 15) << 2;   // 0,4,...,60

    int s = __ldg(src + e);
    int d = __ldg(dst + e);
    float w = __ldg(ew + e);

    const float4 v = *reinterpret_cast<const float4*>(&g_h[(size_t)s * DDIM + lane4]);
    float* o = out + (size_t)d * DDIM + lane4;
    atomicAdd(o + 0, v.x * w);
    atomicAdd(o + 1, v.y * w);
    atomicAdd(o + 2, v.z * w);
    atomicAdd(o + 3, v.w * w);
}

// ---------------------------------------------------------------------------
// Kernel 3: in-place SELU
// ---------------------------------------------------------------------------
__global__ void __launch_bounds__(256) selu_kernel(float* __restrict__ out, int total4)
{
    const float scale = 1.0507009873554805f;
    const float alpha = 1.6732632423543772f;
    int i = blockIdx.x * blockDim.x + threadIdx.x;
    if (i >= total4) return;
    float4 v = reinterpret_cast<float4*>(out)[i];
    v.x = v.x > 0.0f ? scale * v.x : scale * alpha * (expf(v.x) - 1.0f);
    v.y = v.y > 0.0f ? scale * v.y : scale * alpha * (expf(v.y) - 1.0f);
    v.z = v.z > 0.0f ? scale * v.z : scale * alpha * (expf(v.z) - 1.0f);
    v.w = v.w > 0.0f ? scale * v.w : scale * alpha * (expf(v.w) - 1.0f);
    reinterpret_cast<float4*>(out)[i] = v;
}

extern "C" void kernel_launch(void* const* d_in, const int* in_sizes, int n_in,
                              void* d_out, int out_size)
{
    const float* features = (const float*)d_in[0];
    const float* W        = (const float*)d_in[1];
    const float* bias     = (const float*)d_in[2];
    const float* skipw    = (const float*)d_in[3];
    const float* ew       = (const float*)d_in[4];
    const int*   esrc     = (const int*)d_in[5];
    const int*   edst     = (const int*)d_in[6];
    float* out = (float*)d_out;

    const int n = in_sizes[0] / DDIM;     // 50000
    const int E = in_sizes[4];            // 800000

    // 1. GEMM + skip/bias init of accumulator
    int gblocks = (n + 15) / 16;
    gemm_skip_kernel<<<gblocks, 256>>>(features, W, bias, skipw, out, n);

    // 2. scatter-add over edges (16 threads / edge)
    long long threads = (long long)E * 16;
    int sblocks = (int)((threads + 255) / 256);
    scatter_kernel<<<sblocks, 256>>>(ew, esrc, edst, out, E);

    // 3. SELU in place
    int total4 = (n * DDIM) / 4;
    selu_kernel<<<(total4 + 255) / 256, 256>>>(out, total4);
}

// round 2
// speedup vs baseline: 2.5992x; 2.5992x over previous
#include <cuda_runtime.h>
#include <math.h>

#define NMAX 50000
#define DDIM 64
#define SMS 68  // smem row stride (floats): 64 + 4 pad, keeps float4 alignment

// scratch for transformed features h = X @ W^T
__device__ float g_h[(size_t)NMAX * DDIM];

// ---------------------------------------------------------------------------
// Kernel 1: h = X @ W^T ; out = h * skip_weight + bias
// Tile: 64 rows x 64 cols per block, 256 threads, 4x4 register tile/thread.
// smem holds d-major (transposed) X and W tiles -> LDS.128 vector loads.
// ---------------------------------------------------------------------------
__global__ void __launch_bounds__(256) gemm_skip_kernel(
    const float* __restrict__ X,      // (N, 64)
    const float* __restrict__ W,      // (64, 64)  [o][d]
    const float* __restrict__ bias,   // (64)
    const float* __restrict__ skipw,  // (64)
    float* __restrict__ out,          // (N, 64)
    int n)
{
    __shared__ float sW[DDIM * SMS];   // sW[d*SMS + o] = W[o][d]
    __shared__ float sX[DDIM * SMS];   // sX[d*SMS + r] = X[row0+r][d]

    const int tid  = threadIdx.x;
    const int row0 = blockIdx.x * 64;

    // load W transposed: 4096 elems / 256 threads = 16 each (coalesced reads)
    #pragma unroll
    for (int i = 0; i < 16; i++) {
        int idx = tid + i * 256;
        int o = idx >> 6, d = idx & 63;
        sW[d * SMS + o] = W[idx];
    }
    // load X tile transposed
    #pragma unroll
    for (int i = 0; i < 16; i++) {
        int idx = tid + i * 256;
        int r = idx >> 6, d = idx & 63;
        int gr = row0 + r;
        sX[d * SMS + r] = (gr < n) ? X[(size_t)gr * DDIM + d] : 0.0f;
    }
    __syncthreads();

    const int tx = tid & 15;        // col group
    const int ty = tid >> 4;        // row group
    const int o0 = tx * 4;
    const int r0 = ty * 4;

    float acc[4][4];
    #pragma unroll
    for (int i = 0; i < 4; i++)
        #pragma unroll
        for (int j = 0; j < 4; j++) acc[i][j] = 0.0f;

    #pragma unroll 8
    for (int d = 0; d < DDIM; d++) {
        float4 xv = *reinterpret_cast<const float4*>(&sX[d * SMS + r0]);
        float4 wv = *reinterpret_cast<const float4*>(&sW[d * SMS + o0]);
        float x[4] = {xv.x, xv.y, xv.z, xv.w};
        float w[4] = {wv.x, wv.y, wv.z, wv.w};
        #pragma unroll
        for (int i = 0; i < 4; i++)
            #pragma unroll
            for (int j = 0; j < 4; j++)
                acc[i][j] = fmaf(x[i], w[j], acc[i][j]);
    }

    const float4 swv = *reinterpret_cast<const float4*>(&skipw[o0]);
    const float4 bvv = *reinterpret_cast<const float4*>(&bias[o0]);

    #pragma unroll
    for (int i = 0; i < 4; i++) {
        int gr = row0 + r0 + i;
        if (gr < n) {
            float4 hv = make_float4(acc[i][0], acc[i][1], acc[i][2], acc[i][3]);
            *reinterpret_cast<float4*>(&g_h[(size_t)gr * DDIM + o0]) = hv;
            float4 ov;
            ov.x = fmaf(hv.x, swv.x, bvv.x);
            ov.y = fmaf(hv.y, swv.y, bvv.y);
            ov.z = fmaf(hv.z, swv.z, bvv.z);
            ov.w = fmaf(hv.w, swv.w, bvv.w);
            *reinterpret_cast<float4*>(&out[(size_t)gr * DDIM + o0]) = ov;
        }
    }
}

// ---------------------------------------------------------------------------
// Kernel 2: out[dst] += h[src] * w   via red.global.add.v4.f32
// Edge metadata staged in smem (coalesced once), 16 lanes per edge.
// 256 threads, 256 edges per block.
// ---------------------------------------------------------------------------
#define EPB 256

__global__ void __launch_bounds__(256) scatter_kernel(
    const float* __restrict__ ew,
    const int*   __restrict__ src,
    const int*   __restrict__ dst,
    float* __restrict__ out,
    int E)
{
    __shared__ int   es[EPB];
    __shared__ int   ed[EPB];
    __shared__ float ewt[EPB];

    const int tid  = threadIdx.x;
    const int base = blockIdx.x * EPB;

    int ge = base + tid;
    if (ge < E) {
        es[tid]  = src[ge];
        ed[tid]  = dst[ge];
        ewt[tid] = ew[ge];
    }
    __syncthreads();

    const int lane4 = (tid & 15) << 2;   // 0,4,...,60
    const int esub  = tid >> 4;          // 0..15

    #pragma unroll
    for (int p = 0; p < 16; p++) {
        int e = p * 16 + esub;
        if (base + e >= E) break;
        int   s = es[e];
        int   d = ed[e];
        float w = ewt[e];

        const float4 v = *reinterpret_cast<const float4*>(
            &g_h[(size_t)s * DDIM + lane4]);
        float* o = out + (size_t)d * DDIM + lane4;
        asm volatile(
            "red.global.add.v4.f32 [%0], {%1, %2, %3, %4};"
            :: "l"(o), "f"(v.x * w), "f"(v.y * w), "f"(v.z * w), "f"(v.w * w)
            : "memory");
    }
}

// ---------------------------------------------------------------------------
// Kernel 3: in-place SELU
// ---------------------------------------------------------------------------
__global__ void __launch_bounds__(256) selu_kernel(float* __restrict__ out, int total4)
{
    const float scale = 1.0507009873554805f;
    const float alpha = 1.6732632423543772f;
    int i = blockIdx.x * blockDim.x + threadIdx.x;
    if (i >= total4) return;
    float4 v = reinterpret_cast<float4*>(out)[i];
    v.x = v.x > 0.0f ? scale * v.x : scale * alpha * (expf(v.x) - 1.0f);
    v.y = v.y > 0.0f ? scale * v.y : scale * alpha * (expf(v.y) - 1.0f);
    v.z = v.z > 0.0f ? scale * v.z : scale * alpha * (expf(v.z) - 1.0f);
    v.w = v.w > 0.0f ? scale * v.w : scale * alpha * (expf(v.w) - 1.0f);
    reinterpret_cast<float4*>(out)[i] = v;
}

extern "C" void kernel_launch(void* const* d_in, const int* in_sizes, int n_in,
                              void* d_out, int out_size)
{
    const float* features = (const float*)d_in[0];
    const float* W        = (const float*)d_in[1];
    const float* bias     = (const float*)d_in[2];
    const float* skipw    = (const float*)d_in[3];
    const float* ew       = (const float*)d_in[4];
    const int*   esrc     = (const int*)d_in[5];
    const int*   edst     = (const int*)d_in[6];
    float* out = (float*)d_out;

    const int n = in_sizes[0] / DDIM;     // 50000
    const int E = in_sizes[4];            // 800000

    // 1. GEMM + skip/bias init of accumulator
    int gblocks = (n + 63) / 64;
    gemm_skip_kernel<<<gblocks, 256>>>(features, W, bias, skipw, out, n);

    // 2. scatter-add over edges
    int sblocks = (E + EPB - 1) / EPB;
    scatter_kernel<<<sblocks, 256>>>(ew, esrc, edst, out, E);

    // 3. SELU in place
    int total4 = (n * DDIM) / 4;
    selu_kernel<<<(total4 + 255) / 256, 256>>>(out, total4);
}